// round 13
// baseline (speedup 1.0000x reference)
#include <cuda_runtime.h>
#include <cuda_fp16.h>
#include <cstdint>

#define IN_F   4096
#define OUT_F  11008
#define M_TOT  8192

#define BM 128
#define BN 256
#define BK 64
#define NSTAGE 3
#define KT_CNT (IN_F / BK)   // 64
#define ASTR 72              // row stride in halves (128B data + 16B pad)

__device__ __align__(16) __half g_W[(size_t)OUT_F * IN_F];
__device__ __align__(16) __half g_X[(size_t)M_TOT * IN_F];

static __device__ __forceinline__ uint32_t smem_u32(const void* p) {
    return (uint32_t)__cvta_generic_to_shared(p);
}
static __device__ __forceinline__ void cp16(uint32_t dst, const void* src) {
    asm volatile("cp.async.cg.shared.global [%0], [%1], 16;\n" :: "r"(dst), "l"(src));
}
static __device__ __forceinline__ void ldsm4(uint32_t* d, uint32_t addr) {
    asm volatile("ldmatrix.sync.aligned.m8n8.x4.shared.b16 {%0,%1,%2,%3}, [%4];"
        : "=r"(d[0]), "=r"(d[1]), "=r"(d[2]), "=r"(d[3]) : "r"(addr));
}

// ---------------------------------------------------------------------------
// Fused prep: blocks [0, XBLK) do xscale, blocks [XBLK, XBLK+QBLK) do dequant.
// ---------------------------------------------------------------------------
#define XBLK ((M_TOT * IN_F / 8) / 256)              // 16384
#define QBLK ((OUT_F * (IN_F / 2) / 4) / 256)        // 5504

__global__ __launch_bounds__(256)
void prep_kernel(const float* __restrict__ x, const float* __restrict__ iscale,
                 const int* __restrict__ qw, const float* __restrict__ scales,
                 const float* __restrict__ zeros) {
    if (blockIdx.x < XBLK) {
        int idx = blockIdx.x * 256 + threadIdx.x;
        const float4* xp = (const float4*)x;
        float4 a = xp[2 * idx], b = xp[2 * idx + 1];
        int k4 = (2 * idx) & 1023;
        float4 sa = ((const float4*)iscale)[k4];
        float4 sb = ((const float4*)iscale)[k4 + 1];
        uint4 r;
        __half2 h;
        h = __floats2half2_rn(a.x * sa.x, a.y * sa.y); r.x = *reinterpret_cast<uint32_t*>(&h);
        h = __floats2half2_rn(a.z * sa.z, a.w * sa.w); r.y = *reinterpret_cast<uint32_t*>(&h);
        h = __floats2half2_rn(b.x * sb.x, b.y * sb.y); r.z = *reinterpret_cast<uint32_t*>(&h);
        h = __floats2half2_rn(b.z * sb.z, b.w * sb.w); r.w = *reinterpret_cast<uint32_t*>(&h);
        ((uint4*)g_X)[idx] = r;
    } else {
        int idx = (blockIdx.x - XBLK) * 256 + threadIdx.x;
        int4 v = ((const int4*)qw)[idx];
        int o  = idx >> 9;
        int jq = idx & 511;
        int g  = jq >> 4;
        float s  = scales[o * 32 + g];
        float zs = -zeros[o * 32 + g] * s;
        uint4 outv;
        __half2 h;
        h = __floats2half2_rn((float)((v.x >> 4) & 15) * s + zs, (float)(v.x & 15) * s + zs);
        outv.x = *reinterpret_cast<uint32_t*>(&h);
        h = __floats2half2_rn((float)((v.y >> 4) & 15) * s + zs, (float)(v.y & 15) * s + zs);
        outv.y = *reinterpret_cast<uint32_t*>(&h);
        h = __floats2half2_rn((float)((v.z >> 4) & 15) * s + zs, (float)(v.z & 15) * s + zs);
        outv.z = *reinterpret_cast<uint32_t*>(&h);
        h = __floats2half2_rn((float)((v.w >> 4) & 15) * s + zs, (float)(v.w & 15) * s + zs);
        outv.w = *reinterpret_cast<uint32_t*>(&h);
        ((uint4*)g_W)[(size_t)o * 512 + jq] = outv;
    }
}

// ---------------------------------------------------------------------------
// GEMM: BM=128, BN=256, 8 warps (2x4), 64x64 warp tile, BK=64, 3-stage
// cp.async, 1 CTA/SM. One sync per 2.1M MACs (half the R12 sync frequency);
// post-sync path is register-resident so the single-domain bubble stays small.
// ---------------------------------------------------------------------------
__global__ __launch_bounds__(256, 1)
void gemm_kernel(const float* __restrict__ bias, float* __restrict__ C) {
    extern __shared__ __half smem[];
    __half* smA = smem;                         // NSTAGE * BM * ASTR
    __half* smB = smem + NSTAGE * BM * ASTR;    // NSTAGE * BN * ASTR

    const int tid  = threadIdx.x;
    const int lane = tid & 31;
    const int wid  = tid >> 5;
    const int wm   = wid & 1;    // 2 warp rows of 64
    const int wn   = wid >> 1;   // 4 warp cols of 64
    const int m0   = blockIdx.y * BM;
    const int n0   = blockIdx.x * BN;

    const char* gA = (const char*)(g_X + (size_t)m0 * IN_F);
    const char* gB = (const char*)(g_W + (size_t)n0 * IN_F);

    float acc[4][8][4];
    #pragma unroll
    for (int i = 0; i < 4; i++)
        #pragma unroll
        for (int j = 0; j < 8; j++)
            #pragma unroll
            for (int k = 0; k < 4; k++) acc[i][j][k] = 0.f;

    // lane-constant smem read offsets (bytes within a stage); kk adds 32B each
    uint32_t aoffs[4], boffs[4];
    #pragma unroll
    for (int mt = 0; mt < 4; mt++) {
        int row = wm * 64 + mt * 16 + (lane & 15);
        int col = (lane >> 4) * 8;
        aoffs[mt] = (uint32_t)(row * ASTR + col) * 2;
    }
    {
        int mi = lane >> 3, r = lane & 7;
        #pragma unroll
        for (int ntp = 0; ntp < 4; ntp++) {
            int n = wn * 64 + ntp * 16 + (mi >> 1) * 8 + r;
            int k = (mi & 1) * 8;
            boffs[ntp] = (uint32_t)(n * ASTR + k) * 2;
        }
    }

    // loader: per stage A=1024 chunks, B=2048 chunks over 256 threads (4+8 each)
    const int rA = tid >> 3, cA = tid & 7;
    auto issue = [&](int kt, int slot) {
        __half* sA = smA + slot * (BM * ASTR);
        __half* sB = smB + slot * (BN * ASTR);
        size_t koff = (size_t)kt * (BK * 2);   // byte offset in K
        #pragma unroll
        for (int i = 0; i < 4; i++) {          // A: 128 rows
            int r = rA + i * 32;
            cp16(smem_u32(sA + r * ASTR + cA * 8),
                 gA + (size_t)r * (IN_F * 2) + koff + cA * 16);
        }
        #pragma unroll
        for (int i = 0; i < 8; i++) {          // B: 256 rows
            int r = rA + i * 32;
            cp16(smem_u32(sB + r * ASTR + cA * 8),
                 gB + (size_t)r * (IN_F * 2) + koff + cA * 16);
        }
        asm volatile("cp.async.commit_group;\n");
    };

    uint32_t abuf[2][4][4];   // [buf][mt][frag]
    uint32_t bbuf[2][8][2];   // [buf][nt][frag]

    auto loadA = [&](uint32_t (*ab)[4], uint32_t base, uint32_t kkoff) {
        #pragma unroll
        for (int mt = 0; mt < 4; mt++) ldsm4(ab[mt], base + aoffs[mt] + kkoff);
    };
    auto loadB = [&](uint32_t (*bb)[2], uint32_t base, uint32_t kkoff) {
        #pragma unroll
        for (int ntp = 0; ntp < 4; ntp++) {
            uint32_t t[4];
            ldsm4(t, base + boffs[ntp] + kkoff);
            bb[2 * ntp][0] = t[0]; bb[2 * ntp][1] = t[1];
            bb[2 * ntp + 1][0] = t[2]; bb[2 * ntp + 1][1] = t[3];
        }
    };
    auto domma = [&](uint32_t (*ab)[4], uint32_t (*bb)[2]) {
        #pragma unroll
        for (int mt = 0; mt < 4; mt++)
            #pragma unroll
            for (int nt = 0; nt < 8; nt++) {
                asm volatile(
                    "mma.sync.aligned.m16n8k16.row.col.f32.f16.f16.f32 "
                    "{%0,%1,%2,%3}, {%4,%5,%6,%7}, {%8,%9}, {%0,%1,%2,%3};"
                    : "+f"(acc[mt][nt][0]), "+f"(acc[mt][nt][1]),
                      "+f"(acc[mt][nt][2]), "+f"(acc[mt][nt][3])
                    : "r"(ab[mt][0]), "r"(ab[mt][1]), "r"(ab[mt][2]), "r"(ab[mt][3]),
                      "r"(bb[nt][0]), "r"(bb[nt][1]));
            }
    };

    issue(0, 0); issue(1, 1);
    asm volatile("cp.async.wait_group 0;\n");   // slots 0 and 1 complete
    __syncthreads();

    // prime buf0 with (slot 0, kk0)
    loadA(abuf[0], smem_u32(smA), 0);
    loadB(bbuf[0], smem_u32(smB), 0);

    int cslot = 0;   // slot being consumed
    int islot = 2;   // slot to fill this iteration (kt+2)
    for (int kt = 0; kt < KT_CNT; kt++) {
        uint32_t ca = smem_u32(smA + cslot * (BM * ASTR));
        uint32_t cb = smem_u32(smB + cslot * (BN * ASTR));

        // kk1 LDSM first (ahead of the cp.async burst in the LSU queue)
        loadA(abuf[1], ca, 32);
        loadB(bbuf[1], cb, 32);

        if (kt + 2 < KT_CNT) issue(kt + 2, islot);
        else asm volatile("cp.async.commit_group;\n");  // keep group count uniform

        domma(abuf[0], bbuf[0]);           // kk0 (already in regs)

        loadA(abuf[0], ca, 64);
        loadB(bbuf[0], cb, 64);
        domma(abuf[1], bbuf[1]);           // kk1

        loadA(abuf[1], ca, 96);
        loadB(bbuf[1], cb, 96);
        domma(abuf[0], bbuf[0]);           // kk2

        // mid-iteration barrier: groups <= kt+1 complete (1 pending allowed),
        // all warps done reading slot kt (safe to rewrite next iteration).
        asm volatile("cp.async.wait_group 1;\n");
        __syncthreads();

        // cross-tile prefetch: kk0 of slot kt+1 (complete per the wait)
        if (kt + 1 < KT_CNT) {
            int ns = (cslot + 1 == NSTAGE) ? 0 : cslot + 1;
            loadA(abuf[0], smem_u32(smA + ns * (BM * ASTR)), 0);
            loadB(bbuf[0], smem_u32(smB + ns * (BN * ASTR)), 0);
        }
        domma(abuf[1], bbuf[1]);           // kk3

        cslot = (cslot + 1 == NSTAGE) ? 0 : cslot + 1;
        islot = (islot + 1 == NSTAGE) ? 0 : islot + 1;
    }

    #pragma unroll
    for (int mt = 0; mt < 4; mt++) {
        int row = m0 + wm * 64 + mt * 16 + (lane >> 2);
        #pragma unroll
        for (int nt = 0; nt < 8; nt++) {
            int col = n0 + wn * 64 + nt * 8 + (lane & 3) * 2;
            float2 bv = *reinterpret_cast<const float2*>(bias + col);
            float2 v0 = make_float2(acc[mt][nt][0] + bv.x, acc[mt][nt][1] + bv.y);
            float2 v1 = make_float2(acc[mt][nt][2] + bv.x, acc[mt][nt][3] + bv.y);
            *reinterpret_cast<float2*>(C + (size_t)row * OUT_F + col)       = v0;
            *reinterpret_cast<float2*>(C + (size_t)(row + 8) * OUT_F + col) = v1;
        }
    }
}

// ---------------------------------------------------------------------------
extern "C" void kernel_launch(void* const* d_in, const int* in_sizes, int n_in,
                              void* d_out, int out_size) {
    const float* x      = (const float*)d_in[0];
    const int*   qw     = (const int*)  d_in[1];
    const float* scales = (const float*)d_in[2];
    const float* zeros  = (const float*)d_in[3];
    const float* iscale = (const float*)d_in[4];
    const float* bias   = (const float*)d_in[5];
    float* out = (float*)d_out;

    prep_kernel<<<XBLK + QBLK, 256>>>(x, iscale, qw, scales, zeros);

    constexpr int SMEM_BYTES = NSTAGE * (BM + BN) * ASTR * 2;   // 165888
    cudaFuncSetAttribute(gemm_kernel, cudaFuncAttributeMaxDynamicSharedMemorySize, SMEM_BYTES);
    dim3 grid(OUT_F / BN, M_TOT / BM);   // 43 x 64
    gemm_kernel<<<grid, 256, SMEM_BYTES>>>(bias, out);
}

// round 14
// speedup vs baseline: 1.0464x; 1.0464x over previous
#include <cuda_runtime.h>
#include <cuda_fp16.h>
#include <cstdint>

#define IN_F   4096
#define OUT_F  11008
#define M_TOT  8192

#define BM 128
#define BN 128
#define BK 64
#define NSTAGE 3
#define KT_CNT (IN_F / BK)   // 64
#define ASTR 72              // row stride in halves (128B data + 16B pad)

__device__ __align__(16) __half g_W[(size_t)OUT_F * IN_F];
__device__ __align__(16) __half g_X[(size_t)M_TOT * IN_F];

static __device__ __forceinline__ uint32_t smem_u32(const void* p) {
    return (uint32_t)__cvta_generic_to_shared(p);
}
static __device__ __forceinline__ void cp16(uint32_t dst, const void* src) {
    asm volatile("cp.async.cg.shared.global [%0], [%1], 16;\n" :: "r"(dst), "l"(src));
}
static __device__ __forceinline__ void ldsm4(uint32_t* d, uint32_t addr) {
    asm volatile("ldmatrix.sync.aligned.m8n8.x4.shared.b16 {%0,%1,%2,%3}, [%4];"
        : "=r"(d[0]), "=r"(d[1]), "=r"(d[2]), "=r"(d[3]) : "r"(addr));
}

// ---------------------------------------------------------------------------
// Fused prep, 2x coarsened:
//  blocks [0, XBLK): xscale, 16 floats per thread
//  blocks [XBLK, XBLK+QBLK): dequant, 8 packed int32 (16 weights) per thread
// ---------------------------------------------------------------------------
#define XBLK ((M_TOT * IN_F / 16) / 256)             // 8192
#define QBLK ((OUT_F * (IN_F / 2) / 8) / 256)        // 2752

__global__ __launch_bounds__(256)
void prep_kernel(const float* __restrict__ x, const float* __restrict__ iscale,
                 const int* __restrict__ qw, const float* __restrict__ scales,
                 const float* __restrict__ zeros) {
    if (blockIdx.x < XBLK) {
        int idx = blockIdx.x * 256 + threadIdx.x;     // 16 floats per thread
        const float4* xp = (const float4*)x + 4 * (size_t)idx;
        int k4 = (4 * idx) & 1023;                    // float4 index within row
        const float4* sp = (const float4*)iscale + k4;
        uint4 r0, r1;
        __half2 h;
        {
            float4 a = xp[0], sa = sp[0];
            h = __floats2half2_rn(a.x * sa.x, a.y * sa.y); r0.x = *reinterpret_cast<uint32_t*>(&h);
            h = __floats2half2_rn(a.z * sa.z, a.w * sa.w); r0.y = *reinterpret_cast<uint32_t*>(&h);
        }
        {
            float4 a = xp[1], sa = sp[1];
            h = __floats2half2_rn(a.x * sa.x, a.y * sa.y); r0.z = *reinterpret_cast<uint32_t*>(&h);
            h = __floats2half2_rn(a.z * sa.z, a.w * sa.w); r0.w = *reinterpret_cast<uint32_t*>(&h);
        }
        {
            float4 a = xp[2], sa = sp[2];
            h = __floats2half2_rn(a.x * sa.x, a.y * sa.y); r1.x = *reinterpret_cast<uint32_t*>(&h);
            h = __floats2half2_rn(a.z * sa.z, a.w * sa.w); r1.y = *reinterpret_cast<uint32_t*>(&h);
        }
        {
            float4 a = xp[3], sa = sp[3];
            h = __floats2half2_rn(a.x * sa.x, a.y * sa.y); r1.z = *reinterpret_cast<uint32_t*>(&h);
            h = __floats2half2_rn(a.z * sa.z, a.w * sa.w); r1.w = *reinterpret_cast<uint32_t*>(&h);
        }
        ((uint4*)g_X)[2 * idx]     = r0;
        ((uint4*)g_X)[2 * idx + 1] = r1;
    } else {
        int idx = (blockIdx.x - XBLK) * 256 + threadIdx.x;  // 8 int32 per thread
        const int4* qp = (const int4*)qw + 2 * (size_t)idx;
        int o  = idx >> 8;           // 256 8-int32 chunks per row (2048 int32/row)
        int jq = idx & 255;
        int g  = jq >> 3;            // group = (jq*8)/64
        float s  = scales[o * 32 + g];
        float zs = -zeros[o * 32 + g] * s;
        int4 v0 = qp[0], v1 = qp[1];
        uint4 o0, o1;
        __half2 h;
        h = __floats2half2_rn((float)((v0.x >> 4) & 15) * s + zs, (float)(v0.x & 15) * s + zs);
        o0.x = *reinterpret_cast<uint32_t*>(&h);
        h = __floats2half2_rn((float)((v0.y >> 4) & 15) * s + zs, (float)(v0.y & 15) * s + zs);
        o0.y = *reinterpret_cast<uint32_t*>(&h);
        h = __floats2half2_rn((float)((v0.z >> 4) & 15) * s + zs, (float)(v0.z & 15) * s + zs);
        o0.z = *reinterpret_cast<uint32_t*>(&h);
        h = __floats2half2_rn((float)((v0.w >> 4) & 15) * s + zs, (float)(v0.w & 15) * s + zs);
        o0.w = *reinterpret_cast<uint32_t*>(&h);
        h = __floats2half2_rn((float)((v1.x >> 4) & 15) * s + zs, (float)(v1.x & 15) * s + zs);
        o1.x = *reinterpret_cast<uint32_t*>(&h);
        h = __floats2half2_rn((float)((v1.y >> 4) & 15) * s + zs, (float)(v1.y & 15) * s + zs);
        o1.y = *reinterpret_cast<uint32_t*>(&h);
        h = __floats2half2_rn((float)((v1.z >> 4) & 15) * s + zs, (float)(v1.z & 15) * s + zs);
        o1.z = *reinterpret_cast<uint32_t*>(&h);
        h = __floats2half2_rn((float)((v1.w >> 4) & 15) * s + zs, (float)(v1.w & 15) * s + zs);
        o1.w = *reinterpret_cast<uint32_t*>(&h);
        ((uint4*)g_W)[2 * (size_t)idx]     = o0;
        ((uint4*)g_W)[2 * (size_t)idx + 1] = o1;
    }
}

// ---------------------------------------------------------------------------
// GEMM (R12 verbatim — measured best): BM=BN=128, 4 warps (2x2), 64x64 warp
// tile, BK=64, 3-stage cp.async, 2 CTAs/SM, mid-iteration wait_group 1,
// register pipeline across kk and kt.
// ---------------------------------------------------------------------------
__global__ __launch_bounds__(128, 2)
void gemm_kernel(const float* __restrict__ bias, float* __restrict__ C) {
    extern __shared__ __half smem[];
    __half* smA = smem;                         // NSTAGE * BM * ASTR
    __half* smB = smem + NSTAGE * BM * ASTR;    // NSTAGE * BN * ASTR

    const int tid  = threadIdx.x;
    const int lane = tid & 31;
    const int wid  = tid >> 5;
    const int wm   = wid & 1;    // 2 warp rows of 64
    const int wn   = wid >> 1;   // 2 warp cols of 64
    const int m0   = blockIdx.y * BM;
    const int n0   = blockIdx.x * BN;

    const char* gA = (const char*)(g_X + (size_t)m0 * IN_F);
    const char* gB = (const char*)(g_W + (size_t)n0 * IN_F);

    float acc[4][8][4];
    #pragma unroll
    for (int i = 0; i < 4; i++)
        #pragma unroll
        for (int j = 0; j < 8; j++)
            #pragma unroll
            for (int k = 0; k < 4; k++) acc[i][j][k] = 0.f;

    uint32_t aoffs[4], boffs[4];
    #pragma unroll
    for (int mt = 0; mt < 4; mt++) {
        int row = wm * 64 + mt * 16 + (lane & 15);
        int col = (lane >> 4) * 8;
        aoffs[mt] = (uint32_t)(row * ASTR + col) * 2;
    }
    {
        int mi = lane >> 3, r = lane & 7;
        #pragma unroll
        for (int ntp = 0; ntp < 4; ntp++) {
            int n = wn * 64 + ntp * 16 + (mi >> 1) * 8 + r;
            int k = (mi & 1) * 8;
            boffs[ntp] = (uint32_t)(n * ASTR + k) * 2;
        }
    }

    const int rA = tid >> 3, cA = tid & 7;
    auto issue = [&](int kt, int slot) {
        __half* sA = smA + slot * (BM * ASTR);
        __half* sB = smB + slot * (BN * ASTR);
        size_t koff = (size_t)kt * (BK * 2);
        #pragma unroll
        for (int i = 0; i < 8; i++) {
            int r = rA + i * 16;
            cp16(smem_u32(sA + r * ASTR + cA * 8),
                 gA + (size_t)r * (IN_F * 2) + koff + cA * 16);
            cp16(smem_u32(sB + r * ASTR + cA * 8),
                 gB + (size_t)r * (IN_F * 2) + koff + cA * 16);
        }
        asm volatile("cp.async.commit_group;\n");
    };

    uint32_t abuf[2][4][4];
    uint32_t bbuf[2][8][2];

    auto loadA = [&](uint32_t (*ab)[4], uint32_t base, uint32_t kkoff) {
        #pragma unroll
        for (int mt = 0; mt < 4; mt++) ldsm4(ab[mt], base + aoffs[mt] + kkoff);
    };
    auto loadB = [&](uint32_t (*bb)[2], uint32_t base, uint32_t kkoff) {
        #pragma unroll
        for (int ntp = 0; ntp < 4; ntp++) {
            uint32_t t[4];
            ldsm4(t, base + boffs[ntp] + kkoff);
            bb[2 * ntp][0] = t[0]; bb[2 * ntp][1] = t[1];
            bb[2 * ntp + 1][0] = t[2]; bb[2 * ntp + 1][1] = t[3];
        }
    };
    auto domma = [&](uint32_t (*ab)[4], uint32_t (*bb)[2]) {
        #pragma unroll
        for (int mt = 0; mt < 4; mt++)
            #pragma unroll
            for (int nt = 0; nt < 8; nt++) {
                asm volatile(
                    "mma.sync.aligned.m16n8k16.row.col.f32.f16.f16.f32 "
                    "{%0,%1,%2,%3}, {%4,%5,%6,%7}, {%8,%9}, {%0,%1,%2,%3};"
                    : "+f"(acc[mt][nt][0]), "+f"(acc[mt][nt][1]),
                      "+f"(acc[mt][nt][2]), "+f"(acc[mt][nt][3])
                    : "r"(ab[mt][0]), "r"(ab[mt][1]), "r"(ab[mt][2]), "r"(ab[mt][3]),
                      "r"(bb[nt][0]), "r"(bb[nt][1]));
            }
    };

    issue(0, 0); issue(1, 1);
    asm volatile("cp.async.wait_group 0;\n");
    __syncthreads();

    loadA(abuf[0], smem_u32(smA), 0);
    loadB(bbuf[0], smem_u32(smB), 0);

    int cslot = 0;
    int islot = 2;
    for (int kt = 0; kt < KT_CNT; kt++) {
        uint32_t ca = smem_u32(smA + cslot * (BM * ASTR));
        uint32_t cb = smem_u32(smB + cslot * (BN * ASTR));

        loadA(abuf[1], ca, 32);
        loadB(bbuf[1], cb, 32);

        if (kt + 2 < KT_CNT) issue(kt + 2, islot);
        else asm volatile("cp.async.commit_group;\n");

        domma(abuf[0], bbuf[0]);           // kk0

        loadA(abuf[0], ca, 64);
        loadB(bbuf[0], cb, 64);
        domma(abuf[1], bbuf[1]);           // kk1

        loadA(abuf[1], ca, 96);
        loadB(bbuf[1], cb, 96);
        domma(abuf[0], bbuf[0]);           // kk2

        asm volatile("cp.async.wait_group 1;\n");
        __syncthreads();

        if (kt + 1 < KT_CNT) {
            int ns = (cslot + 1 == NSTAGE) ? 0 : cslot + 1;
            loadA(abuf[0], smem_u32(smA + ns * (BM * ASTR)), 0);
            loadB(bbuf[0], smem_u32(smB + ns * (BN * ASTR)), 0);
        }
        domma(abuf[1], bbuf[1]);           // kk3

        cslot = (cslot + 1 == NSTAGE) ? 0 : cslot + 1;
        islot = (islot + 1 == NSTAGE) ? 0 : islot + 1;
    }

    #pragma unroll
    for (int mt = 0; mt < 4; mt++) {
        int row = m0 + wm * 64 + mt * 16 + (lane >> 2);
        #pragma unroll
        for (int nt = 0; nt < 8; nt++) {
            int col = n0 + wn * 64 + nt * 8 + (lane & 3) * 2;
            float2 bv = *reinterpret_cast<const float2*>(bias + col);
            float2 v0 = make_float2(acc[mt][nt][0] + bv.x, acc[mt][nt][1] + bv.y);
            float2 v1 = make_float2(acc[mt][nt][2] + bv.x, acc[mt][nt][3] + bv.y);
            *reinterpret_cast<float2*>(C + (size_t)row * OUT_F + col)       = v0;
            *reinterpret_cast<float2*>(C + (size_t)(row + 8) * OUT_F + col) = v1;
        }
    }
}

// ---------------------------------------------------------------------------
extern "C" void kernel_launch(void* const* d_in, const int* in_sizes, int n_in,
                              void* d_out, int out_size) {
    const float* x      = (const float*)d_in[0];
    const int*   qw     = (const int*)  d_in[1];
    const float* scales = (const float*)d_in[2];
    const float* zeros  = (const float*)d_in[3];
    const float* iscale = (const float*)d_in[4];
    const float* bias   = (const float*)d_in[5];
    float* out = (float*)d_out;

    prep_kernel<<<XBLK + QBLK, 256>>>(x, iscale, qw, scales, zeros);

    constexpr int SMEM_BYTES = NSTAGE * (BM + BN) * ASTR * 2;   // 110592
    cudaFuncSetAttribute(gemm_kernel, cudaFuncAttributeMaxDynamicSharedMemorySize, SMEM_BYTES);
    dim3 grid(OUT_F / BN, M_TOT / BM);   // 86 x 64
    gemm_kernel<<<grid, 128, SMEM_BYTES>>>(bias, out);
}

// round 15
// speedup vs baseline: 1.0495x; 1.0029x over previous
#include <cuda_runtime.h>
#include <cuda_fp16.h>
#include <cstdint>

#define IN_F   4096
#define OUT_F  11008
#define M_TOT  8192

#define BM 128
#define BN 128
#define BK 64
#define NSTAGE 3
#define KT_CNT (IN_F / BK)   // 64
#define ASTR 72              // row stride in halves (128B data + 16B pad)

__device__ __align__(16) __half g_W[(size_t)OUT_F * IN_F];
__device__ __align__(16) __half g_X[(size_t)M_TOT * IN_F];

static __device__ __forceinline__ uint32_t smem_u32(const void* p) {
    return (uint32_t)__cvta_generic_to_shared(p);
}
static __device__ __forceinline__ void cp16(uint32_t dst, const void* src) {
    asm volatile("cp.async.cg.shared.global [%0], [%1], 16;\n" :: "r"(dst), "l"(src));
}
static __device__ __forceinline__ void ldsm4(uint32_t* d, uint32_t addr) {
    asm volatile("ldmatrix.sync.aligned.m8n8.x4.shared.b16 {%0,%1,%2,%3}, [%4];"
        : "=r"(d[0]), "=r"(d[1]), "=r"(d[2]), "=r"(d[3]) : "r"(addr));
}

// ---------------------------------------------------------------------------
// Fused prep (DRAM-floor bound):
//  blocks [0, XBLK): xscale, 16 floats per thread
//  blocks [XBLK, XBLK+QBLK): dequant, 8 packed int32 (16 weights) per thread
// ---------------------------------------------------------------------------
#define XBLK ((M_TOT * IN_F / 16) / 256)             // 8192
#define QBLK ((OUT_F * (IN_F / 2) / 8) / 256)        // 2752

__global__ __launch_bounds__(256)
void prep_kernel(const float* __restrict__ x, const float* __restrict__ iscale,
                 const int* __restrict__ qw, const float* __restrict__ scales,
                 const float* __restrict__ zeros) {
    if (blockIdx.x < XBLK) {
        int idx = blockIdx.x * 256 + threadIdx.x;
        const float4* xp = (const float4*)x + 4 * (size_t)idx;
        int k4 = (4 * idx) & 1023;
        const float4* sp = (const float4*)iscale + k4;
        uint4 r0, r1;
        __half2 h;
        {
            float4 a = xp[0], sa = sp[0];
            h = __floats2half2_rn(a.x * sa.x, a.y * sa.y); r0.x = *reinterpret_cast<uint32_t*>(&h);
            h = __floats2half2_rn(a.z * sa.z, a.w * sa.w); r0.y = *reinterpret_cast<uint32_t*>(&h);
        }
        {
            float4 a = xp[1], sa = sp[1];
            h = __floats2half2_rn(a.x * sa.x, a.y * sa.y); r0.z = *reinterpret_cast<uint32_t*>(&h);
            h = __floats2half2_rn(a.z * sa.z, a.w * sa.w); r0.w = *reinterpret_cast<uint32_t*>(&h);
        }
        {
            float4 a = xp[2], sa = sp[2];
            h = __floats2half2_rn(a.x * sa.x, a.y * sa.y); r1.x = *reinterpret_cast<uint32_t*>(&h);
            h = __floats2half2_rn(a.z * sa.z, a.w * sa.w); r1.y = *reinterpret_cast<uint32_t*>(&h);
        }
        {
            float4 a = xp[3], sa = sp[3];
            h = __floats2half2_rn(a.x * sa.x, a.y * sa.y); r1.z = *reinterpret_cast<uint32_t*>(&h);
            h = __floats2half2_rn(a.z * sa.z, a.w * sa.w); r1.w = *reinterpret_cast<uint32_t*>(&h);
        }
        ((uint4*)g_X)[2 * idx]     = r0;
        ((uint4*)g_X)[2 * idx + 1] = r1;
    } else {
        int idx = (blockIdx.x - XBLK) * 256 + threadIdx.x;
        const int4* qp = (const int4*)qw + 2 * (size_t)idx;
        int o  = idx >> 8;
        int jq = idx & 255;
        int g  = jq >> 3;
        float s  = scales[o * 32 + g];
        float zs = -zeros[o * 32 + g] * s;
        int4 v0 = qp[0], v1 = qp[1];
        uint4 o0, o1;
        __half2 h;
        h = __floats2half2_rn((float)((v0.x >> 4) & 15) * s + zs, (float)(v0.x & 15) * s + zs);
        o0.x = *reinterpret_cast<uint32_t*>(&h);
        h = __floats2half2_rn((float)((v0.y >> 4) & 15) * s + zs, (float)(v0.y & 15) * s + zs);
        o0.y = *reinterpret_cast<uint32_t*>(&h);
        h = __floats2half2_rn((float)((v0.z >> 4) & 15) * s + zs, (float)(v0.z & 15) * s + zs);
        o0.z = *reinterpret_cast<uint32_t*>(&h);
        h = __floats2half2_rn((float)((v0.w >> 4) & 15) * s + zs, (float)(v0.w & 15) * s + zs);
        o0.w = *reinterpret_cast<uint32_t*>(&h);
        h = __floats2half2_rn((float)((v1.x >> 4) & 15) * s + zs, (float)(v1.x & 15) * s + zs);
        o1.x = *reinterpret_cast<uint32_t*>(&h);
        h = __floats2half2_rn((float)((v1.y >> 4) & 15) * s + zs, (float)(v1.y & 15) * s + zs);
        o1.y = *reinterpret_cast<uint32_t*>(&h);
        h = __floats2half2_rn((float)((v1.z >> 4) & 15) * s + zs, (float)(v1.z & 15) * s + zs);
        o1.z = *reinterpret_cast<uint32_t*>(&h);
        h = __floats2half2_rn((float)((v1.w >> 4) & 15) * s + zs, (float)(v1.w & 15) * s + zs);
        o1.w = *reinterpret_cast<uint32_t*>(&h);
        ((uint4*)g_W)[2 * (size_t)idx]     = o0;
        ((uint4*)g_W)[2 * (size_t)idx + 1] = o1;
    }
}

// ---------------------------------------------------------------------------
// GEMM: R12 structure with compile-time slot constants.
// BM=BN=128, 4 warps (2x2), 64x64 warp tile, BK=64, 3-stage cp.async,
// 2 CTAs/SM, mid-iteration wait_group 1. kt loop = 20 triples (slots 0,1,2
// as literals) + peeled 4-iteration epilogue absorbing all boundary branches.
// ---------------------------------------------------------------------------
__global__ __launch_bounds__(128, 2)
void gemm_kernel(const float* __restrict__ bias, float* __restrict__ C) {
    extern __shared__ __half smem[];
    __half* smA = smem;                         // NSTAGE * BM * ASTR
    __half* smB = smem + NSTAGE * BM * ASTR;    // NSTAGE * BN * ASTR

    const int tid  = threadIdx.x;
    const int lane = tid & 31;
    const int wid  = tid >> 5;
    const int wm   = wid & 1;
    const int wn   = wid >> 1;
    const int m0   = blockIdx.y * BM;
    const int n0   = blockIdx.x * BN;

    const char* gA = (const char*)(g_X + (size_t)m0 * IN_F);
    const char* gB = (const char*)(g_W + (size_t)n0 * IN_F);

    float acc[4][8][4];
    #pragma unroll
    for (int i = 0; i < 4; i++)
        #pragma unroll
        for (int j = 0; j < 8; j++)
            #pragma unroll
            for (int k = 0; k < 4; k++) acc[i][j][k] = 0.f;

    uint32_t aoffs[4], boffs[4];
    #pragma unroll
    for (int mt = 0; mt < 4; mt++) {
        int row = wm * 64 + mt * 16 + (lane & 15);
        int col = (lane >> 4) * 8;
        aoffs[mt] = (uint32_t)(row * ASTR + col) * 2;
    }
    {
        int mi = lane >> 3, r = lane & 7;
        #pragma unroll
        for (int ntp = 0; ntp < 4; ntp++) {
            int n = wn * 64 + ntp * 16 + (mi >> 1) * 8 + r;
            int k = (mi & 1) * 8;
            boffs[ntp] = (uint32_t)(n * ASTR + k) * 2;
        }
    }

    // per-slot smem bases (computed once)
    uint32_t baseA[NSTAGE], baseB[NSTAGE];
    #pragma unroll
    for (int s = 0; s < NSTAGE; s++) {
        baseA[s] = smem_u32(smA + s * (BM * ASTR));
        baseB[s] = smem_u32(smB + s * (BN * ASTR));
    }

    const int rA = tid >> 3, cA = tid & 7;
    auto issue = [&](int kt, int slot) {
        __half* sA = smA + slot * (BM * ASTR);
        __half* sB = smB + slot * (BN * ASTR);
        size_t koff = (size_t)kt * (BK * 2);
        #pragma unroll
        for (int i = 0; i < 8; i++) {
            int r = rA + i * 16;
            cp16(smem_u32(sA + r * ASTR + cA * 8),
                 gA + (size_t)r * (IN_F * 2) + koff + cA * 16);
            cp16(smem_u32(sB + r * ASTR + cA * 8),
                 gB + (size_t)r * (IN_F * 2) + koff + cA * 16);
        }
        asm volatile("cp.async.commit_group;\n");
    };

    uint32_t abuf[2][4][4];
    uint32_t bbuf[2][8][2];

    auto loadA = [&](uint32_t (*ab)[4], uint32_t base, uint32_t kkoff) {
        #pragma unroll
        for (int mt = 0; mt < 4; mt++) ldsm4(ab[mt], base + aoffs[mt] + kkoff);
    };
    auto loadB = [&](uint32_t (*bb)[2], uint32_t base, uint32_t kkoff) {
        #pragma unroll
        for (int ntp = 0; ntp < 4; ntp++) {
            uint32_t t[4];
            ldsm4(t, base + boffs[ntp] + kkoff);
            bb[2 * ntp][0] = t[0]; bb[2 * ntp][1] = t[1];
            bb[2 * ntp + 1][0] = t[2]; bb[2 * ntp + 1][1] = t[3];
        }
    };
    auto domma = [&](uint32_t (*ab)[4], uint32_t (*bb)[2]) {
        #pragma unroll
        for (int mt = 0; mt < 4; mt++)
            #pragma unroll
            for (int nt = 0; nt < 8; nt++) {
                asm volatile(
                    "mma.sync.aligned.m16n8k16.row.col.f32.f16.f16.f32 "
                    "{%0,%1,%2,%3}, {%4,%5,%6,%7}, {%8,%9}, {%0,%1,%2,%3};"
                    : "+f"(acc[mt][nt][0]), "+f"(acc[mt][nt][1]),
                      "+f"(acc[mt][nt][2]), "+f"(acc[mt][nt][3])
                    : "r"(ab[mt][0]), "r"(ab[mt][1]), "r"(ab[mt][2]), "r"(ab[mt][3]),
                      "r"(bb[nt][0]), "r"(bb[nt][1]));
            }
    };

    // one pipeline step; cs/ns/doIssue/doPrefetch are compile-time at call sites
    auto step = [&](int kt, int cs, bool doIssue, bool doPrefetch) {
        const int ns = (cs + 1 == NSTAGE) ? 0 : cs + 1;   // slot of kt+1
        const int is = (ns + 1 == NSTAGE) ? 0 : ns + 1;   // slot of kt+2
        uint32_t ca = baseA[cs], cb = baseB[cs];

        loadA(abuf[1], ca, 32);
        loadB(bbuf[1], cb, 32);

        if (doIssue) issue(kt + 2, is);
        else asm volatile("cp.async.commit_group;\n");   // keep group count uniform

        domma(abuf[0], bbuf[0]);           // kk0 (already in regs)

        loadA(abuf[0], ca, 64);
        loadB(bbuf[0], cb, 64);
        domma(abuf[1], bbuf[1]);           // kk1

        loadA(abuf[1], ca, 96);
        loadB(bbuf[1], cb, 96);
        domma(abuf[0], bbuf[0]);           // kk2

        asm volatile("cp.async.wait_group 1;\n");
        __syncthreads();

        if (doPrefetch) {                  // kk0 of slot kt+1 (complete per wait)
            loadA(abuf[0], baseA[ns], 0);
            loadB(bbuf[0], baseB[ns], 0);
        }
        domma(abuf[1], bbuf[1]);           // kk3
    };

    issue(0, 0); issue(1, 1);
    asm volatile("cp.async.wait_group 0;\n");
    __syncthreads();

    loadA(abuf[0], baseA[0], 0);
    loadB(bbuf[0], baseB[0], 0);

    // main loop: kt = 0..59, slots cycle 0,1,2 as literals
    for (int t = 0; t < 20; t++) {
        int kt = 3 * t;
        step(kt + 0, 0, true, true);
        step(kt + 1, 1, true, true);
        step(kt + 2, 2, true, true);
    }
    // epilogue: kt = 60..63 (60%3=0)
    step(60, 0, true,  true);    // issues 62 -> slot 2
    step(61, 1, true,  true);    // issues 63 -> slot 0
    step(62, 2, false, true);
    step(63, 0, false, false);

    #pragma unroll
    for (int mt = 0; mt < 4; mt++) {
        int row = m0 + wm * 64 + mt * 16 + (lane >> 2);
        #pragma unroll
        for (int nt = 0; nt < 8; nt++) {
            int col = n0 + wn * 64 + nt * 8 + (lane & 3) * 2;
            float2 bv = *reinterpret_cast<const float2*>(bias + col);
            float2 v0 = make_float2(acc[mt][nt][0] + bv.x, acc[mt][nt][1] + bv.y);
            float2 v1 = make_float2(acc[mt][nt][2] + bv.x, acc[mt][nt][3] + bv.y);
            *reinterpret_cast<float2*>(C + (size_t)row * OUT_F + col)       = v0;
            *reinterpret_cast<float2*>(C + (size_t)(row + 8) * OUT_F + col) = v1;
        }
    }
}

// ---------------------------------------------------------------------------
extern "C" void kernel_launch(void* const* d_in, const int* in_sizes, int n_in,
                              void* d_out, int out_size) {
    const float* x      = (const float*)d_in[0];
    const int*   qw     = (const int*)  d_in[1];
    const float* scales = (const float*)d_in[2];
    const float* zeros  = (const float*)d_in[3];
    const float* iscale = (const float*)d_in[4];
    const float* bias   = (const float*)d_in[5];
    float* out = (float*)d_out;

    prep_kernel<<<XBLK + QBLK, 256>>>(x, iscale, qw, scales, zeros);

    constexpr int SMEM_BYTES = NSTAGE * (BM + BN) * ASTR * 2;   // 110592
    cudaFuncSetAttribute(gemm_kernel, cudaFuncAttributeMaxDynamicSharedMemorySize, SMEM_BYTES);
    dim3 grid(OUT_F / BN, M_TOT / BM);   // 86 x 64
    gemm_kernel<<<grid, 128, SMEM_BYTES>>>(bias, out);
}

// round 16
// speedup vs baseline: 1.0891x; 1.0377x over previous
#include <cuda_runtime.h>
#include <cuda_fp16.h>
#include <cstdint>

#define IN_F   4096
#define OUT_F  11008
#define M_TOT  8192

#define BM 128
#define BN 128
#define BK 64
#define NSTAGE 3
#define KT_CNT (IN_F / BK)   // 64
#define ASTR 72              // row stride in halves (128B data + 16B pad)

__device__ __align__(16) __half g_W[(size_t)OUT_F * IN_F];
__device__ __align__(16) __half g_X[(size_t)M_TOT * IN_F];

static __device__ __forceinline__ uint32_t smem_u32(const void* p) {
    return (uint32_t)__cvta_generic_to_shared(p);
}
static __device__ __forceinline__ void cp16(uint32_t dst, const void* src) {
    asm volatile("cp.async.cg.shared.global [%0], [%1], 16;\n" :: "r"(dst), "l"(src));
}
static __device__ __forceinline__ void ldsm4(uint32_t* d, uint32_t addr) {
    asm volatile("ldmatrix.sync.aligned.m8n8.x4.shared.b16 {%0,%1,%2,%3}, [%4];"
        : "=r"(d[0]), "=r"(d[1]), "=r"(d[2]), "=r"(d[3]) : "r"(addr));
}

// ---------------------------------------------------------------------------
// Fused prep (DRAM-floor bound):
//  blocks [0, XBLK): xscale, 16 floats per thread
//  blocks [XBLK, XBLK+QBLK): dequant, 8 packed int32 (16 weights) per thread
// ---------------------------------------------------------------------------
#define XBLK ((M_TOT * IN_F / 16) / 256)             // 8192
#define QBLK ((OUT_F * (IN_F / 2) / 8) / 256)        // 2752

__global__ __launch_bounds__(256)
void prep_kernel(const float* __restrict__ x, const float* __restrict__ iscale,
                 const int* __restrict__ qw, const float* __restrict__ scales,
                 const float* __restrict__ zeros) {
    if (blockIdx.x < XBLK) {
        int idx = blockIdx.x * 256 + threadIdx.x;
        const float4* xp = (const float4*)x + 4 * (size_t)idx;
        int k4 = (4 * idx) & 1023;
        const float4* sp = (const float4*)iscale + k4;
        uint4 r0, r1;
        __half2 h;
        {
            float4 a = xp[0], sa = sp[0];
            h = __floats2half2_rn(a.x * sa.x, a.y * sa.y); r0.x = *reinterpret_cast<uint32_t*>(&h);
            h = __floats2half2_rn(a.z * sa.z, a.w * sa.w); r0.y = *reinterpret_cast<uint32_t*>(&h);
        }
        {
            float4 a = xp[1], sa = sp[1];
            h = __floats2half2_rn(a.x * sa.x, a.y * sa.y); r0.z = *reinterpret_cast<uint32_t*>(&h);
            h = __floats2half2_rn(a.z * sa.z, a.w * sa.w); r0.w = *reinterpret_cast<uint32_t*>(&h);
        }
        {
            float4 a = xp[2], sa = sp[2];
            h = __floats2half2_rn(a.x * sa.x, a.y * sa.y); r1.x = *reinterpret_cast<uint32_t*>(&h);
            h = __floats2half2_rn(a.z * sa.z, a.w * sa.w); r1.y = *reinterpret_cast<uint32_t*>(&h);
        }
        {
            float4 a = xp[3], sa = sp[3];
            h = __floats2half2_rn(a.x * sa.x, a.y * sa.y); r1.z = *reinterpret_cast<uint32_t*>(&h);
            h = __floats2half2_rn(a.z * sa.z, a.w * sa.w); r1.w = *reinterpret_cast<uint32_t*>(&h);
        }
        ((uint4*)g_X)[2 * idx]     = r0;
        ((uint4*)g_X)[2 * idx + 1] = r1;
    } else {
        int idx = (blockIdx.x - XBLK) * 256 + threadIdx.x;
        const int4* qp = (const int4*)qw + 2 * (size_t)idx;
        int o  = idx >> 8;
        int jq = idx & 255;
        int g  = jq >> 3;
        float s  = scales[o * 32 + g];
        float zs = -zeros[o * 32 + g] * s;
        int4 v0 = qp[0], v1 = qp[1];
        uint4 o0, o1;
        __half2 h;
        h = __floats2half2_rn((float)((v0.x >> 4) & 15) * s + zs, (float)(v0.x & 15) * s + zs);
        o0.x = *reinterpret_cast<uint32_t*>(&h);
        h = __floats2half2_rn((float)((v0.y >> 4) & 15) * s + zs, (float)(v0.y & 15) * s + zs);
        o0.y = *reinterpret_cast<uint32_t*>(&h);
        h = __floats2half2_rn((float)((v0.z >> 4) & 15) * s + zs, (float)(v0.z & 15) * s + zs);
        o0.z = *reinterpret_cast<uint32_t*>(&h);
        h = __floats2half2_rn((float)((v0.w >> 4) & 15) * s + zs, (float)(v0.w & 15) * s + zs);
        o0.w = *reinterpret_cast<uint32_t*>(&h);
        h = __floats2half2_rn((float)((v1.x >> 4) & 15) * s + zs, (float)(v1.x & 15) * s + zs);
        o1.x = *reinterpret_cast<uint32_t*>(&h);
        h = __floats2half2_rn((float)((v1.y >> 4) & 15) * s + zs, (float)(v1.y & 15) * s + zs);
        o1.y = *reinterpret_cast<uint32_t*>(&h);
        h = __floats2half2_rn((float)((v1.z >> 4) & 15) * s + zs, (float)(v1.z & 15) * s + zs);
        o1.z = *reinterpret_cast<uint32_t*>(&h);
        h = __floats2half2_rn((float)((v1.w >> 4) & 15) * s + zs, (float)(v1.w & 15) * s + zs);
        o1.w = *reinterpret_cast<uint32_t*>(&h);
        ((uint4*)g_W)[2 * (size_t)idx]     = o0;
        ((uint4*)g_W)[2 * (size_t)idx + 1] = o1;
    }
}

// ---------------------------------------------------------------------------
// GEMM: R15 structure + cp.async burst split into two 8-op halves smeared
// between MMA chunks (LSU burst no longer blocks a warp's HMMA issue window).
// BM=BN=128, 4 warps (2x2), 64x64 warp tile, BK=64, 3-stage, 2 CTAs/SM,
// mid-iteration wait_group 1, compile-time slot constants.
// ---------------------------------------------------------------------------
__global__ __launch_bounds__(128, 2)
void gemm_kernel(const float* __restrict__ bias, float* __restrict__ C) {
    extern __shared__ __half smem[];
    __half* smA = smem;                         // NSTAGE * BM * ASTR
    __half* smB = smem + NSTAGE * BM * ASTR;    // NSTAGE * BN * ASTR

    const int tid  = threadIdx.x;
    const int lane = tid & 31;
    const int wid  = tid >> 5;
    const int wm   = wid & 1;
    const int wn   = wid >> 1;
    const int m0   = blockIdx.y * BM;
    const int n0   = blockIdx.x * BN;

    const char* gA = (const char*)(g_X + (size_t)m0 * IN_F);
    const char* gB = (const char*)(g_W + (size_t)n0 * IN_F);

    float acc[4][8][4];
    #pragma unroll
    for (int i = 0; i < 4; i++)
        #pragma unroll
        for (int j = 0; j < 8; j++)
            #pragma unroll
            for (int k = 0; k < 4; k++) acc[i][j][k] = 0.f;

    uint32_t aoffs[4], boffs[4];
    #pragma unroll
    for (int mt = 0; mt < 4; mt++) {
        int row = wm * 64 + mt * 16 + (lane & 15);
        int col = (lane >> 4) * 8;
        aoffs[mt] = (uint32_t)(row * ASTR + col) * 2;
    }
    {
        int mi = lane >> 3, r = lane & 7;
        #pragma unroll
        for (int ntp = 0; ntp < 4; ntp++) {
            int n = wn * 64 + ntp * 16 + (mi >> 1) * 8 + r;
            int k = (mi & 1) * 8;
            boffs[ntp] = (uint32_t)(n * ASTR + k) * 2;
        }
    }

    uint32_t baseA[NSTAGE], baseB[NSTAGE];
    #pragma unroll
    for (int s = 0; s < NSTAGE; s++) {
        baseA[s] = smem_u32(smA + s * (BM * ASTR));
        baseB[s] = smem_u32(smB + s * (BN * ASTR));
    }

    const int rA = tid >> 3, cA = tid & 7;
    // half = 0: rows rA+{0,16,32,48}; half = 1: rows rA+{64,80,96,112}
    auto issue_half = [&](int kt, int slot, int half) {
        __half* sA = smA + slot * (BM * ASTR);
        __half* sB = smB + slot * (BN * ASTR);
        size_t koff = (size_t)kt * (BK * 2);
        #pragma unroll
        for (int i = 4 * half; i < 4 * half + 4; i++) {
            int r = rA + i * 16;
            cp16(smem_u32(sA + r * ASTR + cA * 8),
                 gA + (size_t)r * (IN_F * 2) + koff + cA * 16);
            cp16(smem_u32(sB + r * ASTR + cA * 8),
                 gB + (size_t)r * (IN_F * 2) + koff + cA * 16);
        }
    };

    uint32_t abuf[2][4][4];
    uint32_t bbuf[2][8][2];

    auto loadA = [&](uint32_t (*ab)[4], uint32_t base, uint32_t kkoff) {
        #pragma unroll
        for (int mt = 0; mt < 4; mt++) ldsm4(ab[mt], base + aoffs[mt] + kkoff);
    };
    auto loadB = [&](uint32_t (*bb)[2], uint32_t base, uint32_t kkoff) {
        #pragma unroll
        for (int ntp = 0; ntp < 4; ntp++) {
            uint32_t t[4];
            ldsm4(t, base + boffs[ntp] + kkoff);
            bb[2 * ntp][0] = t[0]; bb[2 * ntp][1] = t[1];
            bb[2 * ntp + 1][0] = t[2]; bb[2 * ntp + 1][1] = t[3];
        }
    };
    auto domma = [&](uint32_t (*ab)[4], uint32_t (*bb)[2]) {
        #pragma unroll
        for (int mt = 0; mt < 4; mt++)
            #pragma unroll
            for (int nt = 0; nt < 8; nt++) {
                asm volatile(
                    "mma.sync.aligned.m16n8k16.row.col.f32.f16.f16.f32 "
                    "{%0,%1,%2,%3}, {%4,%5,%6,%7}, {%8,%9}, {%0,%1,%2,%3};"
                    : "+f"(acc[mt][nt][0]), "+f"(acc[mt][nt][1]),
                      "+f"(acc[mt][nt][2]), "+f"(acc[mt][nt][3])
                    : "r"(ab[mt][0]), "r"(ab[mt][1]), "r"(ab[mt][2]), "r"(ab[mt][3]),
                      "r"(bb[nt][0]), "r"(bb[nt][1]));
            }
    };

    // one pipeline step; cs/doIssue/doPrefetch compile-time at call sites
    auto step = [&](int kt, int cs, bool doIssue, bool doPrefetch) {
        const int ns = (cs + 1 == NSTAGE) ? 0 : cs + 1;   // slot of kt+1
        const int is = (ns + 1 == NSTAGE) ? 0 : ns + 1;   // slot of kt+2
        uint32_t ca = baseA[cs], cb = baseB[cs];

        loadA(abuf[1], ca, 32);
        loadB(bbuf[1], cb, 32);

        domma(abuf[0], bbuf[0]);           // kk0 (already in regs)

        if (doIssue) issue_half(kt + 2, is, 0);   // first 8 cp.async, covered by kk1

        loadA(abuf[0], ca, 64);
        loadB(bbuf[0], cb, 64);
        domma(abuf[1], bbuf[1]);           // kk1

        if (doIssue) issue_half(kt + 2, is, 1);   // second 8 cp.async, covered by kk2
        asm volatile("cp.async.commit_group;\n");  // exactly one commit per step

        loadA(abuf[1], ca, 96);
        loadB(bbuf[1], cb, 96);
        domma(abuf[0], bbuf[0]);           // kk2

        asm volatile("cp.async.wait_group 1;\n");
        __syncthreads();

        if (doPrefetch) {                  // kk0 of slot kt+1 (complete per wait)
            loadA(abuf[0], baseA[ns], 0);
            loadB(bbuf[0], baseB[ns], 0);
        }
        domma(abuf[1], bbuf[1]);           // kk3
    };

    // prologue: fill slots 0 and 1
    issue_half(0, 0, 0); issue_half(0, 0, 1);
    asm volatile("cp.async.commit_group;\n");
    issue_half(1, 1, 0); issue_half(1, 1, 1);
    asm volatile("cp.async.commit_group;\n");
    asm volatile("cp.async.wait_group 0;\n");
    __syncthreads();

    loadA(abuf[0], baseA[0], 0);
    loadB(bbuf[0], baseB[0], 0);

    // main loop: kt = 0..59, slots cycle 0,1,2 as literals
    for (int t = 0; t < 20; t++) {
        int kt = 3 * t;
        step(kt + 0, 0, true, true);
        step(kt + 1, 1, true, true);
        step(kt + 2, 2, true, true);
    }
    // epilogue: kt = 60..63 (60%3=0)
    step(60, 0, true,  true);    // issues 62 -> slot 2
    step(61, 1, true,  true);    // issues 63 -> slot 0
    step(62, 2, false, true);
    step(63, 0, false, false);

    #pragma unroll
    for (int mt = 0; mt < 4; mt++) {
        int row = m0 + wm * 64 + mt * 16 + (lane >> 2);
        #pragma unroll
        for (int nt = 0; nt < 8; nt++) {
            int col = n0 + wn * 64 + nt * 8 + (lane & 3) * 2;
            float2 bv = *reinterpret_cast<const float2*>(bias + col);
            float2 v0 = make_float2(acc[mt][nt][0] + bv.x, acc[mt][nt][1] + bv.y);
            float2 v1 = make_float2(acc[mt][nt][2] + bv.x, acc[mt][nt][3] + bv.y);
            *reinterpret_cast<float2*>(C + (size_t)row * OUT_F + col)       = v0;
            *reinterpret_cast<float2*>(C + (size_t)(row + 8) * OUT_F + col) = v1;
        }
    }
}

// ---------------------------------------------------------------------------
extern "C" void kernel_launch(void* const* d_in, const int* in_sizes, int n_in,
                              void* d_out, int out_size) {
    const float* x      = (const float*)d_in[0];
    const int*   qw     = (const int*)  d_in[1];
    const float* scales = (const float*)d_in[2];
    const float* zeros  = (const float*)d_in[3];
    const float* iscale = (const float*)d_in[4];
    const float* bias   = (const float*)d_in[5];
    float* out = (float*)d_out;

    prep_kernel<<<XBLK + QBLK, 256>>>(x, iscale, qw, scales, zeros);

    constexpr int SMEM_BYTES = NSTAGE * (BM + BN) * ASTR * 2;   // 110592
    cudaFuncSetAttribute(gemm_kernel, cudaFuncAttributeMaxDynamicSharedMemorySize, SMEM_BYTES);
    dim3 grid(OUT_F / BN, M_TOT / BM);   // 86 x 64
    gemm_kernel<<<grid, 128, SMEM_BYTES>>>(bias, out);
}

// round 17
// speedup vs baseline: 1.0942x; 1.0048x over previous
#include <cuda_runtime.h>
#include <cuda_fp16.h>
#include <cstdint>

#define IN_F   4096
#define OUT_F  11008
#define M_TOT  8192

#define BM 128
#define BN 128
#define BK 64
#define NSTAGE 3
#define KT_CNT (IN_F / BK)   // 64
#define ASTR 72              // row stride in halves (128B data + 16B pad)

__device__ __align__(16) __half g_W[(size_t)OUT_F * IN_F];
__device__ __align__(16) __half g_X[(size_t)M_TOT * IN_F];

static __device__ __forceinline__ uint32_t smem_u32(const void* p) {
    return (uint32_t)__cvta_generic_to_shared(p);
}
static __device__ __forceinline__ void cp16(uint32_t dst, const void* src) {
    asm volatile("cp.async.cg.shared.global [%0], [%1], 16;\n" :: "r"(dst), "l"(src));
}
static __device__ __forceinline__ void ldsm4(uint32_t* d, uint32_t addr) {
    asm volatile("ldmatrix.sync.aligned.m8n8.x4.shared.b16 {%0,%1,%2,%3}, [%4];"
        : "=r"(d[0]), "=r"(d[1]), "=r"(d[2]), "=r"(d[3]) : "r"(addr));
}

// ---------------------------------------------------------------------------
// Fused prep (DRAM-floor bound):
//  blocks [0, XBLK): xscale, 16 floats per thread
//  blocks [XBLK, XBLK+QBLK): dequant, 8 packed int32 (16 weights) per thread
// ---------------------------------------------------------------------------
#define XBLK ((M_TOT * IN_F / 16) / 256)             // 8192
#define QBLK ((OUT_F * (IN_F / 2) / 8) / 256)        // 2752

__global__ __launch_bounds__(256)
void prep_kernel(const float* __restrict__ x, const float* __restrict__ iscale,
                 const int* __restrict__ qw, const float* __restrict__ scales,
                 const float* __restrict__ zeros) {
    if (blockIdx.x < XBLK) {
        int idx = blockIdx.x * 256 + threadIdx.x;
        const float4* xp = (const float4*)x + 4 * (size_t)idx;
        int k4 = (4 * idx) & 1023;
        const float4* sp = (const float4*)iscale + k4;
        uint4 r0, r1;
        __half2 h;
        {
            float4 a = xp[0], sa = sp[0];
            h = __floats2half2_rn(a.x * sa.x, a.y * sa.y); r0.x = *reinterpret_cast<uint32_t*>(&h);
            h = __floats2half2_rn(a.z * sa.z, a.w * sa.w); r0.y = *reinterpret_cast<uint32_t*>(&h);
        }
        {
            float4 a = xp[1], sa = sp[1];
            h = __floats2half2_rn(a.x * sa.x, a.y * sa.y); r0.z = *reinterpret_cast<uint32_t*>(&h);
            h = __floats2half2_rn(a.z * sa.z, a.w * sa.w); r0.w = *reinterpret_cast<uint32_t*>(&h);
        }
        {
            float4 a = xp[2], sa = sp[2];
            h = __floats2half2_rn(a.x * sa.x, a.y * sa.y); r1.x = *reinterpret_cast<uint32_t*>(&h);
            h = __floats2half2_rn(a.z * sa.z, a.w * sa.w); r1.y = *reinterpret_cast<uint32_t*>(&h);
        }
        {
            float4 a = xp[3], sa = sp[3];
            h = __floats2half2_rn(a.x * sa.x, a.y * sa.y); r1.z = *reinterpret_cast<uint32_t*>(&h);
            h = __floats2half2_rn(a.z * sa.z, a.w * sa.w); r1.w = *reinterpret_cast<uint32_t*>(&h);
        }
        ((uint4*)g_X)[2 * idx]     = r0;
        ((uint4*)g_X)[2 * idx + 1] = r1;
    } else {
        int idx = (blockIdx.x - XBLK) * 256 + threadIdx.x;
        const int4* qp = (const int4*)qw + 2 * (size_t)idx;
        int o  = idx >> 8;
        int jq = idx & 255;
        int g  = jq >> 3;
        float s  = scales[o * 32 + g];
        float zs = -zeros[o * 32 + g] * s;
        int4 v0 = qp[0], v1 = qp[1];
        uint4 o0, o1;
        __half2 h;
        h = __floats2half2_rn((float)((v0.x >> 4) & 15) * s + zs, (float)(v0.x & 15) * s + zs);
        o0.x = *reinterpret_cast<uint32_t*>(&h);
        h = __floats2half2_rn((float)((v0.y >> 4) & 15) * s + zs, (float)(v0.y & 15) * s + zs);
        o0.y = *reinterpret_cast<uint32_t*>(&h);
        h = __floats2half2_rn((float)((v0.z >> 4) & 15) * s + zs, (float)(v0.z & 15) * s + zs);
        o0.z = *reinterpret_cast<uint32_t*>(&h);
        h = __floats2half2_rn((float)((v0.w >> 4) & 15) * s + zs, (float)(v0.w & 15) * s + zs);
        o0.w = *reinterpret_cast<uint32_t*>(&h);
        h = __floats2half2_rn((float)((v1.x >> 4) & 15) * s + zs, (float)(v1.x & 15) * s + zs);
        o1.x = *reinterpret_cast<uint32_t*>(&h);
        h = __floats2half2_rn((float)((v1.y >> 4) & 15) * s + zs, (float)(v1.y & 15) * s + zs);
        o1.y = *reinterpret_cast<uint32_t*>(&h);
        h = __floats2half2_rn((float)((v1.z >> 4) & 15) * s + zs, (float)(v1.z & 15) * s + zs);
        o1.z = *reinterpret_cast<uint32_t*>(&h);
        h = __floats2half2_rn((float)((v1.w >> 4) & 15) * s + zs, (float)(v1.w & 15) * s + zs);
        o1.w = *reinterpret_cast<uint32_t*>(&h);
        ((uint4*)g_W)[2 * (size_t)idx]     = o0;
        ((uint4*)g_W)[2 * (size_t)idx + 1] = o1;
    }
}

// ---------------------------------------------------------------------------
// GEMM: R16 + fine-grain LDSM/MMA interleave (2 LDSM between 8-MMA groups so
// per-warp LDSM issue windows never starve the tensor pipe).
// BM=BN=128, 4 warps (2x2), 64x64 warp tile, BK=64, 3-stage, 2 CTAs/SM,
// mid-iteration wait_group 1, compile-time slot constants, split cp.async.
// ---------------------------------------------------------------------------
__global__ __launch_bounds__(128, 2)
void gemm_kernel(const float* __restrict__ bias, float* __restrict__ C) {
    extern __shared__ __half smem[];
    __half* smA = smem;                         // NSTAGE * BM * ASTR
    __half* smB = smem + NSTAGE * BM * ASTR;    // NSTAGE * BN * ASTR

    const int tid  = threadIdx.x;
    const int lane = tid & 31;
    const int wid  = tid >> 5;
    const int wm   = wid & 1;
    const int wn   = wid >> 1;
    const int m0   = blockIdx.y * BM;
    const int n0   = blockIdx.x * BN;

    const char* gA = (const char*)(g_X + (size_t)m0 * IN_F);
    const char* gB = (const char*)(g_W + (size_t)n0 * IN_F);

    float acc[4][8][4];
    #pragma unroll
    for (int i = 0; i < 4; i++)
        #pragma unroll
        for (int j = 0; j < 8; j++)
            #pragma unroll
            for (int k = 0; k < 4; k++) acc[i][j][k] = 0.f;

    uint32_t aoffs[4], boffs[4];
    #pragma unroll
    for (int mt = 0; mt < 4; mt++) {
        int row = wm * 64 + mt * 16 + (lane & 15);
        int col = (lane >> 4) * 8;
        aoffs[mt] = (uint32_t)(row * ASTR + col) * 2;
    }
    {
        int mi = lane >> 3, r = lane & 7;
        #pragma unroll
        for (int ntp = 0; ntp < 4; ntp++) {
            int n = wn * 64 + ntp * 16 + (mi >> 1) * 8 + r;
            int k = (mi & 1) * 8;
            boffs[ntp] = (uint32_t)(n * ASTR + k) * 2;
        }
    }

    uint32_t baseA[NSTAGE], baseB[NSTAGE];
    #pragma unroll
    for (int s = 0; s < NSTAGE; s++) {
        baseA[s] = smem_u32(smA + s * (BM * ASTR));
        baseB[s] = smem_u32(smB + s * (BN * ASTR));
    }

    const int rA = tid >> 3, cA = tid & 7;
    // half = 0: rows rA+{0,16,32,48}; half = 1: rows rA+{64,80,96,112}
    auto issue_half = [&](int kt, int slot, int half) {
        __half* sA = smA + slot * (BM * ASTR);
        __half* sB = smB + slot * (BN * ASTR);
        size_t koff = (size_t)kt * (BK * 2);
        #pragma unroll
        for (int i = 4 * half; i < 4 * half + 4; i++) {
            int r = rA + i * 16;
            cp16(smem_u32(sA + r * ASTR + cA * 8),
                 gA + (size_t)r * (IN_F * 2) + koff + cA * 16);
            cp16(smem_u32(sB + r * ASTR + cA * 8),
                 gB + (size_t)r * (IN_F * 2) + koff + cA * 16);
        }
    };

    uint32_t abuf[2][4][4];
    uint32_t bbuf[2][8][2];

    auto loadA1 = [&](uint32_t (*ab)[4], int mt, uint32_t base, uint32_t kkoff) {
        ldsm4(ab[mt], base + aoffs[mt] + kkoff);
    };
    auto loadB1 = [&](uint32_t (*bb)[2], int ntp, uint32_t base, uint32_t kkoff) {
        uint32_t t[4];
        ldsm4(t, base + boffs[ntp] + kkoff);
        bb[2 * ntp][0] = t[0]; bb[2 * ntp][1] = t[1];
        bb[2 * ntp + 1][0] = t[2]; bb[2 * ntp + 1][1] = t[3];
    };

    auto mma_row = [&](int mt, uint32_t (*ab)[4], uint32_t (*bb)[2]) {
        #pragma unroll
        for (int nt = 0; nt < 8; nt++) {
            asm volatile(
                "mma.sync.aligned.m16n8k16.row.col.f32.f16.f16.f32 "
                "{%0,%1,%2,%3}, {%4,%5,%6,%7}, {%8,%9}, {%0,%1,%2,%3};"
                : "+f"(acc[mt][nt][0]), "+f"(acc[mt][nt][1]),
                  "+f"(acc[mt][nt][2]), "+f"(acc[mt][nt][3])
                : "r"(ab[mt][0]), "r"(ab[mt][1]), "r"(ab[mt][2]), "r"(ab[mt][3]),
                  "r"(bb[nt][0]), "r"(bb[nt][1]));
        }
    };

    // MMA current chunk while loading next chunk, 2 LDSM per 8-MMA group
    auto fused = [&](uint32_t (*cab)[4], uint32_t (*cbb)[2],
                     uint32_t (*nab)[4], uint32_t (*nbb)[2],
                     uint32_t bA, uint32_t bB, uint32_t kkoff, bool doLoad) {
        #pragma unroll
        for (int mt = 0; mt < 4; mt++) {
            if (doLoad) {
                loadA1(nab, mt, bA, kkoff);
                loadB1(nbb, mt, bB, kkoff);
            }
            mma_row(mt, cab, cbb);
        }
    };

    // one pipeline step; cs/doIssue/doPrefetch compile-time at call sites
    auto step = [&](int kt, int cs, bool doIssue, bool doPrefetch) {
        const int ns = (cs + 1 == NSTAGE) ? 0 : cs + 1;   // slot of kt+1
        const int is = (ns + 1 == NSTAGE) ? 0 : ns + 1;   // slot of kt+2
        uint32_t ca = baseA[cs], cb = baseB[cs];

        // MMA kk0 (in buf0), load kk1 -> buf1
        fused(abuf[0], bbuf[0], abuf[1], bbuf[1], ca, cb, 32, true);

        if (doIssue) issue_half(kt + 2, is, 0);

        // MMA kk1 (buf1), load kk2 -> buf0
        fused(abuf[1], bbuf[1], abuf[0], bbuf[0], ca, cb, 64, true);

        if (doIssue) issue_half(kt + 2, is, 1);
        asm volatile("cp.async.commit_group;\n");   // exactly one commit per step

        // MMA kk2 (buf0), load kk3 -> buf1
        fused(abuf[0], bbuf[0], abuf[1], bbuf[1], ca, cb, 96, true);

        asm volatile("cp.async.wait_group 1;\n");
        __syncthreads();

        // MMA kk3 (buf1), prefetch next tile kk0 -> buf0 (slot ns complete)
        fused(abuf[1], bbuf[1], abuf[0], bbuf[0], baseA[ns], baseB[ns], 0, doPrefetch);
    };

    // prologue: fill slots 0 and 1
    issue_half(0, 0, 0); issue_half(0, 0, 1);
    asm volatile("cp.async.commit_group;\n");
    issue_half(1, 1, 0); issue_half(1, 1, 1);
    asm volatile("cp.async.commit_group;\n");
    asm volatile("cp.async.wait_group 0;\n");
    __syncthreads();

    #pragma unroll
    for (int mt = 0; mt < 4; mt++) {
        loadA1(abuf[0], mt, baseA[0], 0);
        loadB1(bbuf[0], mt, baseB[0], 0);
    }

    // main loop: kt = 0..59, slots cycle 0,1,2 as literals
    for (int t = 0; t < 20; t++) {
        int kt = 3 * t;
        step(kt + 0, 0, true, true);
        step(kt + 1, 1, true, true);
        step(kt + 2, 2, true, true);
    }
    // epilogue: kt = 60..63 (60%3=0)
    step(60, 0, true,  true);    // issues 62 -> slot 2
    step(61, 1, true,  true);    // issues 63 -> slot 0
    step(62, 2, false, true);
    step(63, 0, false, false);

    #pragma unroll
    for (int mt = 0; mt < 4; mt++) {
        int row = m0 + wm * 64 + mt * 16 + (lane >> 2);
        #pragma unroll
        for (int nt = 0; nt < 8; nt++) {
            int col = n0 + wn * 64 + nt * 8 + (lane & 3) * 2;
            float2 bv = *reinterpret_cast<const float2*>(bias + col);
            float2 v0 = make_float2(acc[mt][nt][0] + bv.x, acc[mt][nt][1] + bv.y);
            float2 v1 = make_float2(acc[mt][nt][2] + bv.x, acc[mt][nt][3] + bv.y);
            *reinterpret_cast<float2*>(C + (size_t)row * OUT_F + col)       = v0;
            *reinterpret_cast<float2*>(C + (size_t)(row + 8) * OUT_F + col) = v1;
        }
    }
}

// ---------------------------------------------------------------------------
extern "C" void kernel_launch(void* const* d_in, const int* in_sizes, int n_in,
                              void* d_out, int out_size) {
    const float* x      = (const float*)d_in[0];
    const int*   qw     = (const int*)  d_in[1];
    const float* scales = (const float*)d_in[2];
    const float* zeros  = (const float*)d_in[3];
    const float* iscale = (const float*)d_in[4];
    const float* bias   = (const float*)d_in[5];
    float* out = (float*)d_out;

    prep_kernel<<<XBLK + QBLK, 256>>>(x, iscale, qw, scales, zeros);

    constexpr int SMEM_BYTES = NSTAGE * (BM + BN) * ASTR * 2;   // 110592
    cudaFuncSetAttribute(gemm_kernel, cudaFuncAttributeMaxDynamicSharedMemorySize, SMEM_BYTES);
    dim3 grid(OUT_F / BN, M_TOT / BM);   // 86 x 64
    gemm_kernel<<<grid, 128, SMEM_BYTES>>>(bias, out);
}